// round 6
// baseline (speedup 1.0000x reference)
#include <cuda_runtime.h>
#include <cstdint>
#include <math.h>

#define BBATCH 4
#define SSEQ   2048
#define EEMB   1024
#define HHEADS 16
#define DDIM   64
#define MMROWS (BBATCH*SSEQ)   // 8192

// Scratch (no allocations allowed)
__device__ float g_Q[(size_t)BBATCH*HHEADS*SSEQ*DDIM];
__device__ float g_K[(size_t)BBATCH*HHEADS*SSEQ*DDIM];
__device__ float g_V[(size_t)BBATCH*HHEADS*SSEQ*DDIM];
__device__ float g_A[(size_t)BBATCH*SSEQ*EEMB];

// ---------------------------------------------------------------- helpers
__device__ __forceinline__ uint32_t smem_u32(const void* p){
    uint32_t a;
    asm("{ .reg .u64 t; cvta.to.shared.u64 t, %1; cvt.u32.u64 %0, t; }"
        : "=r"(a) : "l"(p));
    return a;
}
__device__ __forceinline__ float f2tf32f(float x){
    uint32_t u; asm("cvt.rna.tf32.f32 %0, %1;" : "=r"(u) : "f"(x));
    return __uint_as_float(u);
}
__device__ __forceinline__ void cpa16(uint32_t dst, const void* src){
    asm volatile("cp.async.cg.shared.global [%0], [%1], 16;" :: "r"(dst), "l"(src));
}
#define CP_COMMIT() asm volatile("cp.async.commit_group;" ::: "memory")
#define CP_WAIT(n)  asm volatile("cp.async.wait_group %0;" :: "n"(n) : "memory")

// ldmatrix x4: four 8-row x 16B matrices -> 4 regs
__device__ __forceinline__ void ldsm4(uint32_t* r, uint32_t addr){
    asm volatile("ldmatrix.sync.aligned.m8n8.x4.shared.b16 {%0,%1,%2,%3}, [%4];"
        : "=r"(r[0]), "=r"(r[1]), "=r"(r[2]), "=r"(r[3]) : "r"(addr));
}

// D += A(16x8,tf32) * B(8x8,tf32), fp32 accum
__device__ __forceinline__ void mma8(float* d, const uint32_t* a, const uint32_t* b){
    asm volatile("mma.sync.aligned.m16n8k8.row.col.f32.tf32.tf32.f32 "
        "{%0,%1,%2,%3},{%4,%5,%6,%7},{%8,%9},{%0,%1,%2,%3};"
        : "+f"(d[0]), "+f"(d[1]), "+f"(d[2]), "+f"(d[3])
        : "r"(a[0]), "r"(a[1]), "r"(a[2]), "r"(a[3]), "r"(b[0]), "r"(b[1]));
}

// ---------------------------------------------------------------------------
// GEMM core: out = A(Mx1024) @ W(Nx1024)^T + bias.  CTA 256x128, BK=32,
// 3-stage cp.async pipeline.  8 warps (4m x 2n), warp tile 64x64.
// ---------------------------------------------------------------------------
#define GSTR 36                 // stride 144B == 16 mod 128 -> LDSM conflict-free
#define GTA  (256*GSTR)         // A floats per stage
#define GTBB (128*GSTR)         // B floats per stage

__device__ __forceinline__ void gemm_core(
    const float* __restrict__ A, const float* __restrict__ W,
    const float* __restrict__ bias, float* __restrict__ out,
    int scatter, int round_out, float* sm)
{
    float* sA = sm;               // [3][GTA]
    float* sB = sm + 3*GTA;       // [3][GTBB]
    const uint32_t sAu = smem_u32(sA), sBu = smem_u32(sB);

    const int tid = threadIdx.x;
    const int wid = tid >> 5, lane = tid & 31;
    const int g = lane >> 2, t = lane & 3;
    const int lane7 = lane & 7, mat = lane >> 3;
    const int wm = (wid >> 1) * 64, wn = (wid & 1) * 64;
    const int m0 = blockIdx.y * 256, n0 = blockIdx.x * 128;

    // per-lane LDSM byte offsets
    const uint32_t aoff = ((uint32_t)((wm + (mat&1)*8 + lane7) * GSTR + (mat>>1)*4)) * 4u;
    const uint32_t boff = ((uint32_t)((wn + (mat>>1)*8 + lane7) * GSTR + (mat&1)*4)) * 4u;

    float acc[4][8][4] = {};

    auto prefetch = [&](int kc, int st){
        #pragma unroll
        for (int it = 0; it < 8; ++it){          // A: 256 rows
            const int f = tid + it*256;
            const int r = f >> 3, c4 = f & 7;
            cpa16(sAu + (uint32_t)(st*GTA + r*GSTR + c4*4)*4u,
                  A + (size_t)(m0 + r) * EEMB + kc*32 + c4*4);
        }
        #pragma unroll
        for (int it = 0; it < 4; ++it){          // B: 128 rows
            const int f = tid + it*256;
            const int r = f >> 3, c4 = f & 7;
            cpa16(sBu + (uint32_t)(st*GTBB + r*GSTR + c4*4)*4u,
                  W + (size_t)(n0 + r) * EEMB + kc*32 + c4*4);
        }
        CP_COMMIT();
    };

    prefetch(0, 0);
    prefetch(1, 1);
    for (int kc = 0; kc < 32; ++kc){
        if (kc < 31) { CP_WAIT(1); } else { CP_WAIT(0); }
        __syncthreads();
        if (kc + 2 < 32) prefetch(kc + 2, (kc + 2) % 3);
        const int st = kc % 3;
        const uint32_t abase = sAu + (uint32_t)(st*GTA)*4u + aoff;
        const uint32_t bbase = sBu + (uint32_t)(st*GTBB)*4u + boff;
        #pragma unroll
        for (int kk = 0; kk < 4; ++kk){
            uint32_t af[4][4], bf[4][4];
            #pragma unroll
            for (int mi = 0; mi < 4; ++mi)
                ldsm4(af[mi], abase + mi*(16*GSTR*4) + kk*32);
            #pragma unroll
            for (int p = 0; p < 4; ++p)
                ldsm4(bf[p], bbase + p*(16*GSTR*4) + kk*32);
            #pragma unroll
            for (int mi = 0; mi < 4; ++mi)
                #pragma unroll
                for (int p = 0; p < 4; ++p){
                    mma8(acc[mi][2*p],     af[mi], bf[p]);
                    mma8(acc[mi][2*p + 1], af[mi], bf[p] + 2);
                }
        }
    }

    // epilogue
    #pragma unroll
    for (int mi = 0; mi < 4; ++mi){
        #pragma unroll
        for (int ni = 0; ni < 8; ++ni){
            const int n = n0 + wn + ni*8 + t*2;
            const float bv0 = bias[n], bv1 = bias[n+1];
            #pragma unroll
            for (int rr = 0; rr < 2; ++rr){
                const int m = m0 + wm + mi*16 + g + rr*8;
                float v0 = acc[mi][ni][rr*2 + 0] + bv0;
                float v1 = acc[mi][ni][rr*2 + 1] + bv1;
                if (round_out){ v0 = f2tf32f(v0); v1 = f2tf32f(v1); }
                float* op;
                if (scatter){
                    const int b = m >> 11, s = m & 2047;
                    const int h = n >> 6, d = n & 63;
                    op = out + ((size_t)(b*HHEADS + h) * SSEQ + s) * DDIM + d;
                } else {
                    op = out + (size_t)m * EEMB + n;
                }
                *(float2*)op = make_float2(v0, v1);
            }
        }
    }
}

__global__ __launch_bounds__(256, 1)
void gemm_qkv(const float* __restrict__ x,
              const float* __restrict__ Wq, const float* __restrict__ bq,
              const float* __restrict__ Wk, const float* __restrict__ bk,
              const float* __restrict__ Wv, const float* __restrict__ bv,
              float* __restrict__ q, float* __restrict__ k, float* __restrict__ v)
{
    extern __shared__ float sm[];
    if      (blockIdx.z == 0) gemm_core(x, Wq, bq, q, 1, 1, sm);
    else if (blockIdx.z == 1) gemm_core(x, Wk, bk, k, 1, 1, sm);
    else                      gemm_core(x, Wv, bv, v, 1, 1, sm);
}

__global__ __launch_bounds__(256, 1)
void gemm_out(const float* __restrict__ A, const float* __restrict__ W,
              const float* __restrict__ b, float* __restrict__ out)
{
    extern __shared__ float sm[];
    gemm_core(A, W, b, out, 0, 0, sm);
}

// ---------------------------------------------------------------------------
// Attention: per (b,h), 128q x 128k tiles.  Double-buffered K, pipelined V,
// separate P buffer, ldmatrix fragment loads.  2 barriers per k-tile.
// ---------------------------------------------------------------------------
#define KSTR 68    // 272B == 16 mod 128 -> LDSM conflict-free
#define PSTR 132   // 528B == 16 mod 128
#define KTB  (128*KSTR)

__global__ __launch_bounds__(256)
void attn_mma(const float* __restrict__ Q, const float* __restrict__ K,
              const float* __restrict__ V, float* __restrict__ Out)
{
    extern __shared__ float sm[];
    float* sQ = sm;                    // 128*KSTR
    float* sK = sm + KTB;              // [2][128*KSTR]
    float* sV = sm + 3*KTB;            // 128*KSTR
    float* sP = sm + 4*KTB;            // 128*PSTR
    __shared__ float rowsum[128];
    const uint32_t sQu = smem_u32(sQ), sKu = smem_u32(sK), sVu = smem_u32(sV);
    const uint32_t sPu = smem_u32(sP);

    const int tid = threadIdx.x;
    const int wid = tid >> 5, lane = tid & 31;
    const int g = lane >> 2, t = lane & 3;
    const int lane7 = lane & 7, mat = lane >> 3;
    const int wm = (wid >> 2) * 64, wn_s = (wid & 3) * 32, wn_o = (wid & 3) * 16;
    const int q0 = blockIdx.x * 128;
    const int bh = blockIdx.y;
    const int b = bh >> 4, h = bh & 15;

    const float* Qp = Q + (size_t)bh * SSEQ * DDIM;
    const float* Kp = K + (size_t)bh * SSEQ * DDIM;
    const float* Vp = V + (size_t)bh * SSEQ * DDIM;

    if (tid < 128) rowsum[tid] = 0.f;

    const uint32_t qoff = ((uint32_t)((wm   + (mat&1)*8 + lane7) * KSTR + (mat>>1)*4)) * 4u;
    const uint32_t koff = ((uint32_t)((wn_s + (mat>>1)*8 + lane7) * KSTR + (mat&1)*4)) * 4u;
    const uint32_t poff = ((uint32_t)((wm   + (mat&1)*8 + lane7) * PSTR + (mat>>1)*4)) * 4u;

    auto loadK = [&](int kt, int buf){
        const float* Kg = Kp + (size_t)kt * 128 * DDIM;
        #pragma unroll
        for (int it = 0; it < 8; ++it){
            const int f = tid + it*256;
            const int r = f >> 4, c4 = f & 15;
            cpa16(sKu + (uint32_t)(buf*KTB + r*KSTR + c4*4)*4u,
                  Kg + (size_t)r*DDIM + c4*4);
        }
        CP_COMMIT();
    };
    auto loadV = [&](int kt){
        const float* Vg = Vp + (size_t)kt * 128 * DDIM;
        #pragma unroll
        for (int it = 0; it < 8; ++it){
            const int f = tid + it*256;
            const int r = f >> 4, c4 = f & 15;
            cpa16(sVu + (uint32_t)(r*KSTR + c4*4)*4u,
                  Vg + (size_t)r*DDIM + c4*4);
        }
        CP_COMMIT();
    };

    // Q tile
    #pragma unroll
    for (int it = 0; it < 8; ++it){
        const int f = tid + it*256;
        const int r = f >> 4, c4 = f & 15;
        cpa16(sQu + (uint32_t)(r*KSTR + c4*4)*4u, Qp + (size_t)(q0 + r)*DDIM + c4*4);
    }
    CP_COMMIT();
    loadK(0, 0);
    loadV(0);

    float acc_o[4][2][4] = {};
    float lsum[4][2] = {};

    for (int kt = 0; kt < 16; ++kt){
        // wait K(kt) (leaves V(kt) / K(kt+1) in flight)
        CP_WAIT(1);
        __syncthreads();
        if (kt + 1 < 16) loadK(kt + 1, (kt + 1) & 1);

        // S = Q K^T
        const uint32_t kbase = sKu + (uint32_t)((kt & 1) * KTB) * 4u + koff;
        const uint32_t qbase = sQu + qoff;
        float s[4][4][4] = {};
        #pragma unroll
        for (int kk = 0; kk < 8; ++kk){
            uint32_t qa[4][4], kq0[4], kq1[4];
            #pragma unroll
            for (int mi = 0; mi < 4; ++mi)
                ldsm4(qa[mi], qbase + mi*(16*KSTR*4) + kk*32);
            ldsm4(kq0, kbase + kk*32);
            ldsm4(kq1, kbase + 16*KSTR*4 + kk*32);
            #pragma unroll
            for (int mi = 0; mi < 4; ++mi){
                mma8(s[mi][0], qa[mi], kq0);
                mma8(s[mi][1], qa[mi], kq0 + 2);
                mma8(s[mi][2], qa[mi], kq1);
                mma8(s[mi][3], qa[mi], kq1 + 2);
            }
        }

        // P = exp(S/32) = exp2(S * 0.03125*log2e)
        #pragma unroll
        for (int mi = 0; mi < 4; ++mi){
            #pragma unroll
            for (int ni = 0; ni < 4; ++ni){
                #pragma unroll
                for (int rr = 0; rr < 2; ++rr){
                    const int row = wm + mi*16 + g + rr*8;
                    const float e0 = exp2f(s[mi][ni][rr*2 + 0] * 0.04508422002777998f);
                    const float e1 = exp2f(s[mi][ni][rr*2 + 1] * 0.04508422002777998f);
                    lsum[mi][rr] += e0 + e1;
                    const int col = wn_s + ni*8 + t*2;
                    *(float2*)(sP + row*PSTR + col) =
                        make_float2(f2tf32f(e0), f2tf32f(e1));
                }
            }
        }

        // wait V(kt) (leaves K(kt+1) in flight), make P + V visible
        if (kt < 15) { CP_WAIT(1); } else { CP_WAIT(0); }
        __syncthreads();

        // O += P V
        const uint32_t pbase = sPu + poff;
        #pragma unroll
        for (int kk = 0; kk < 16; ++kk){
            uint32_t pa[4][4], vb[2][2];
            #pragma unroll
            for (int mi = 0; mi < 4; ++mi)
                ldsm4(pa[mi], pbase + mi*(16*PSTR*4) + kk*32);
            #pragma unroll
            for (int ni = 0; ni < 2; ++ni){
                const float* br = sV + (kk*8 + t)*KSTR + wn_o + ni*8 + g;
                vb[ni][0] = __float_as_uint(br[0]);
                vb[ni][1] = __float_as_uint(br[4*KSTR]);
            }
            #pragma unroll
            for (int mi = 0; mi < 4; ++mi){
                mma8(acc_o[mi][0], pa[mi], vb[0]);
                mma8(acc_o[mi][1], pa[mi], vb[1]);
            }
        }
        if (kt + 1 < 16) loadV(kt + 1);
    }

    // reduce row sums across the 4 n-warps
    #pragma unroll
    for (int mi = 0; mi < 4; ++mi){
        #pragma unroll
        for (int rr = 0; rr < 2; ++rr){
            float v = lsum[mi][rr];
            v += __shfl_xor_sync(0xffffffffu, v, 1);
            v += __shfl_xor_sync(0xffffffffu, v, 2);
            if (t == 0) atomicAdd(&rowsum[wm + mi*16 + g + rr*8], v);
        }
    }
    __syncthreads();

    // normalize and write O (pre-round tf32 for output gemm)
    #pragma unroll
    for (int mi = 0; mi < 4; ++mi){
        #pragma unroll
        for (int rr = 0; rr < 2; ++rr){
            const int row = wm + mi*16 + g + rr*8;
            const float inv = 1.0f / rowsum[row];
            float* orow = Out + ((size_t)(b * SSEQ + q0 + row)) * EEMB + h * DDIM;
            #pragma unroll
            for (int ni = 0; ni < 2; ++ni){
                const int col = wn_o + ni*8 + t*2;
                const float v0 = f2tf32f(acc_o[mi][ni][rr*2 + 0] * inv);
                const float v1 = f2tf32f(acc_o[mi][ni][rr*2 + 1] * inv);
                *(float2*)(orow + col) = make_float2(v0, v1);
            }
        }
    }
}

// ---------------------------------------------------------------------------
extern "C" void kernel_launch(void* const* d_in, const int* in_sizes, int n_in,
                              void* d_out, int out_size)
{
    const float* x  = (const float*)d_in[0];
    const float* Wq = (const float*)d_in[1];
    const float* bq = (const float*)d_in[2];
    const float* Wk = (const float*)d_in[3];
    const float* bk = (const float*)d_in[4];
    const float* Wv = (const float*)d_in[5];
    const float* bv = (const float*)d_in[6];
    const float* Wo = (const float*)d_in[7];
    const float* bo = (const float*)d_in[8];
    float* out = (float*)d_out;

    float *qp, *kp, *vp, *ap;
    cudaGetSymbolAddress((void**)&qp, g_Q);
    cudaGetSymbolAddress((void**)&kp, g_K);
    cudaGetSymbolAddress((void**)&vp, g_V);
    cudaGetSymbolAddress((void**)&ap, g_A);

    const int gemm_smem = 3 * (GTA + GTBB) * (int)sizeof(float);        // 165888
    const int attn_smem = (4*KTB + 128*PSTR) * (int)sizeof(float);      // 206848
    cudaFuncSetAttribute(gemm_qkv, cudaFuncAttributeMaxDynamicSharedMemorySize, gemm_smem);
    cudaFuncSetAttribute(gemm_out, cudaFuncAttributeMaxDynamicSharedMemorySize, gemm_smem);
    cudaFuncSetAttribute(attn_mma, cudaFuncAttributeMaxDynamicSharedMemorySize, attn_smem);

    dim3 gq(EEMB/128, MMROWS/256, 3);   // 8 x 32 x 3
    gemm_qkv<<<gq, 256, gemm_smem>>>(x, Wq, bq, Wk, bk, Wv, bv, qp, kp, vp);

    dim3 ga(SSEQ/128, BBATCH*HHEADS);   // 16 x 64
    attn_mma<<<ga, 256, attn_smem>>>(qp, kp, vp, ap);

    dim3 gg(EEMB/128, MMROWS/256);      // 8 x 32
    gemm_out<<<gg, 256, gemm_smem>>>(ap, Wo, bo, out);
}

// round 7
// speedup vs baseline: 1.0981x; 1.0981x over previous
#include <cuda_runtime.h>
#include <cstdint>
#include <math.h>

#define BBATCH 4
#define SSEQ   2048
#define EEMB   1024
#define HHEADS 16
#define DDIM   64
#define MMROWS (BBATCH*SSEQ)   // 8192

// Scratch (no allocations allowed)
__device__ float g_Q[(size_t)BBATCH*HHEADS*SSEQ*DDIM];
__device__ float g_K[(size_t)BBATCH*HHEADS*SSEQ*DDIM];
__device__ float g_V[(size_t)BBATCH*HHEADS*SSEQ*DDIM];
__device__ float g_A[(size_t)BBATCH*SSEQ*EEMB];

// ---------------------------------------------------------------- helpers
__device__ __forceinline__ uint32_t smem_u32(const void* p){
    uint32_t a;
    asm("{ .reg .u64 t; cvta.to.shared.u64 t, %1; cvt.u32.u64 %0, t; }"
        : "=r"(a) : "l"(p));
    return a;
}
__device__ __forceinline__ float f2tf32f(float x){
    uint32_t u; asm("cvt.rna.tf32.f32 %0, %1;" : "=r"(u) : "f"(x));
    return __uint_as_float(u);
}
__device__ __forceinline__ void cpa16(uint32_t dst, const void* src){
    asm volatile("cp.async.cg.shared.global [%0], [%1], 16;" :: "r"(dst), "l"(src));
}
#define CP_COMMIT() asm volatile("cp.async.commit_group;" ::: "memory")
#define CP_WAIT(n)  asm volatile("cp.async.wait_group %0;" :: "n"(n) : "memory")

// ldmatrix x4: four 8-row x 16B matrices -> 4 regs
__device__ __forceinline__ void ldsm4(uint32_t* r, uint32_t addr){
    asm volatile("ldmatrix.sync.aligned.m8n8.x4.shared.b16 {%0,%1,%2,%3}, [%4];"
        : "=r"(r[0]), "=r"(r[1]), "=r"(r[2]), "=r"(r[3]) : "r"(addr));
}

// D += A(16x8,tf32) * B(8x8,tf32), fp32 accum
__device__ __forceinline__ void mma8(float* d, const uint32_t* a, const uint32_t* b){
    asm volatile("mma.sync.aligned.m16n8k8.row.col.f32.tf32.tf32.f32 "
        "{%0,%1,%2,%3},{%4,%5,%6,%7},{%8,%9},{%0,%1,%2,%3};"
        : "+f"(d[0]), "+f"(d[1]), "+f"(d[2]), "+f"(d[3])
        : "r"(a[0]), "r"(a[1]), "r"(a[2]), "r"(a[3]), "r"(b[0]), "r"(b[1]));
}

// ---------------------------------------------------------------------------
// GEMM (round-5 config): out = A(Mx1024) @ W(Nx1024)^T + bias.  CTA 128x128,
// BK=32, 3-stage cp.async pipeline, 8 warps 64x32, ldmatrix feeds, 2 CTA/SM.
// ---------------------------------------------------------------------------
#define GSTR 36                 // 144B == 16 mod 128 -> LDSM conflict-free
#define GTB  (128*GSTR)

__device__ __forceinline__ void gemm_core(
    const float* __restrict__ A, const float* __restrict__ W,
    const float* __restrict__ bias, float* __restrict__ out,
    int scatter, int round_out, float* sm)
{
    float* sA = sm;             // [3][GTB]
    float* sB = sm + 3*GTB;     // [3][GTB]
    const uint32_t sAu = smem_u32(sA), sBu = smem_u32(sB);

    const int tid = threadIdx.x;
    const int wid = tid >> 5, lane = tid & 31;
    const int g = lane >> 2, t = lane & 3;
    const int lane7 = lane & 7, mat = lane >> 3;
    const int wm = (wid >> 2) * 64, wn = (wid & 3) * 32;
    const int m0 = blockIdx.y * 128, n0 = blockIdx.x * 128;

    const uint32_t aoff = ((uint32_t)((wm + (mat&1)*8 + lane7) * GSTR + (mat>>1)*4)) * 4u;
    const uint32_t boff = ((uint32_t)((wn + (mat>>1)*8 + lane7) * GSTR + (mat&1)*4)) * 4u;

    float acc[4][4][4] = {};

    auto prefetch = [&](int kc, int st){
        #pragma unroll
        for (int it = 0; it < 4; ++it){
            const int f = tid + it*256;
            const int r = f >> 3, c4 = f & 7;
            const uint32_t so = (uint32_t)(st*GTB + r*GSTR + c4*4) * 4u;
            cpa16(sAu + so, A + (size_t)(m0 + r) * EEMB + kc*32 + c4*4);
            cpa16(sBu + so, W + (size_t)(n0 + r) * EEMB + kc*32 + c4*4);
        }
        CP_COMMIT();
    };

    prefetch(0, 0);
    prefetch(1, 1);
    for (int kc = 0; kc < 32; ++kc){
        if (kc < 31) { CP_WAIT(1); } else { CP_WAIT(0); }
        __syncthreads();
        if (kc + 2 < 32) prefetch(kc + 2, (kc + 2) % 3);
        const uint32_t stb = (uint32_t)((kc % 3) * GTB) * 4u;
        const uint32_t abase = sAu + stb + aoff;
        const uint32_t bbase = sBu + stb + boff;
        #pragma unroll
        for (int kk = 0; kk < 4; ++kk){
            uint32_t af[4][4], bq0[4], bq1[4];
            #pragma unroll
            for (int mi = 0; mi < 4; ++mi)
                ldsm4(af[mi], abase + mi*(16*GSTR*4) + kk*32);
            ldsm4(bq0, bbase + kk*32);
            ldsm4(bq1, bbase + 16*GSTR*4 + kk*32);
            #pragma unroll
            for (int mi = 0; mi < 4; ++mi){
                mma8(acc[mi][0], af[mi], bq0);
                mma8(acc[mi][1], af[mi], bq0 + 2);
                mma8(acc[mi][2], af[mi], bq1);
                mma8(acc[mi][3], af[mi], bq1 + 2);
            }
        }
    }

    #pragma unroll
    for (int mi = 0; mi < 4; ++mi){
        #pragma unroll
        for (int ni = 0; ni < 4; ++ni){
            const int n = n0 + wn + ni*8 + t*2;
            const float bv0 = bias[n], bv1 = bias[n+1];
            #pragma unroll
            for (int rr = 0; rr < 2; ++rr){
                const int m = m0 + wm + mi*16 + g + rr*8;
                float v0 = acc[mi][ni][rr*2 + 0] + bv0;
                float v1 = acc[mi][ni][rr*2 + 1] + bv1;
                if (round_out){ v0 = f2tf32f(v0); v1 = f2tf32f(v1); }
                float* op;
                if (scatter){
                    const int b = m >> 11, s = m & 2047;
                    const int h = n >> 6, d = n & 63;
                    op = out + ((size_t)(b*HHEADS + h) * SSEQ + s) * DDIM + d;
                } else {
                    op = out + (size_t)m * EEMB + n;
                }
                *(float2*)op = make_float2(v0, v1);
            }
        }
    }
}

__global__ __launch_bounds__(256)
void gemm_qkv(const float* __restrict__ x,
              const float* __restrict__ Wq, const float* __restrict__ bq,
              const float* __restrict__ Wk, const float* __restrict__ bk,
              const float* __restrict__ Wv, const float* __restrict__ bv,
              float* __restrict__ q, float* __restrict__ k, float* __restrict__ v)
{
    extern __shared__ float sm[];
    if      (blockIdx.z == 0) gemm_core(x, Wq, bq, q, 1, 1, sm);
    else if (blockIdx.z == 1) gemm_core(x, Wk, bk, k, 1, 1, sm);
    else                      gemm_core(x, Wv, bv, v, 1, 1, sm);
}

__global__ __launch_bounds__(256)
void gemm_out(const float* __restrict__ A, const float* __restrict__ W,
              const float* __restrict__ b, float* __restrict__ out)
{
    extern __shared__ float sm[];
    gemm_core(A, W, b, out, 0, 0, sm);
}

// ---------------------------------------------------------------------------
// Attention, register-P version.  8 warps = 4 m-groups (32q) x 2 key-groups
// (64k).  Per 128-key tile: ONE barrier.  S accumulators are exp'ed and
// shuffle-permuted into PV A-fragments (no P smem round-trip).  K,V double-
// buffered via one cp.async group per tile.  Partial O reduced across the
// key-warp pair at the end through dead K smem.
// ---------------------------------------------------------------------------
#define KSTR 68           // Q/K row stride (floats); 272B == 16 mod 128
#define VSTR 72           // V row stride; (t*8+g)%32 unique -> conflict-free
#define QTB  (128*KSTR)   // 8704 floats
#define VTB  (128*VSTR)   // 9216 floats

__global__ __launch_bounds__(256)
void attn_mma(const float* __restrict__ Q, const float* __restrict__ K,
              const float* __restrict__ V, float* __restrict__ Out)
{
    extern __shared__ float sm[];
    float* sQ = sm;                    // QTB
    float* sK = sm + QTB;              // [2][QTB]  (also O-reduction scratch)
    float* sV = sm + 3*QTB;            // [2][VTB]
    __shared__ float rowsum[128];
    const uint32_t sQu = smem_u32(sQ), sKu = smem_u32(sK), sVu = smem_u32(sV);

    const int tid = threadIdx.x;
    const int wid = tid >> 5, lane = tid & 31;
    const int g = lane >> 2, t = lane & 3;
    const int lane7 = lane & 7, mat = lane >> 3;
    const int wm = (wid >> 1) * 32;        // 4 m-groups of 32 rows
    const int wk = (wid & 1) * 64;         // 2 key-groups of 64 keys
    const int q0 = blockIdx.x * 128;
    const int bh = blockIdx.y;
    const int b = bh >> 4, h = bh & 15;

    const float* Qp = Q + (size_t)bh * SSEQ * DDIM;
    const float* Kp = K + (size_t)bh * SSEQ * DDIM;
    const float* Vp = V + (size_t)bh * SSEQ * DDIM;

    if (tid < 128) rowsum[tid] = 0.f;

    const uint32_t qoff = ((uint32_t)((wm + (mat&1)*8 + lane7) * KSTR + (mat>>1)*4)) * 4u;
    const uint32_t koff = ((uint32_t)((wk + (mat>>1)*8 + lane7) * KSTR + (mat&1)*4)) * 4u;

    auto loadKV = [&](int kt, int buf){
        const float* Kg = Kp + (size_t)kt * 128 * DDIM;
        const float* Vg = Vp + (size_t)kt * 128 * DDIM;
        #pragma unroll
        for (int it = 0; it < 8; ++it){
            const int f = tid + it*256;
            const int r = f >> 4, c4 = f & 15;
            cpa16(sKu + (uint32_t)(buf*QTB + r*KSTR + c4*4)*4u, Kg + (size_t)r*DDIM + c4*4);
            cpa16(sVu + (uint32_t)(buf*VTB + r*VSTR + c4*4)*4u, Vg + (size_t)r*DDIM + c4*4);
        }
        CP_COMMIT();
    };

    // prologue: Q + K0 + V0 in one group
    #pragma unroll
    for (int it = 0; it < 8; ++it){
        const int f = tid + it*256;
        const int r = f >> 4, c4 = f & 15;
        cpa16(sQu + (uint32_t)(r*KSTR + c4*4)*4u, Qp + (size_t)(q0 + r)*DDIM + c4*4);
    }
    {
        const float* Kg = Kp;
        const float* Vg = Vp;
        #pragma unroll
        for (int it = 0; it < 8; ++it){
            const int f = tid + it*256;
            const int r = f >> 4, c4 = f & 15;
            cpa16(sKu + (uint32_t)(r*KSTR + c4*4)*4u, Kg + (size_t)r*DDIM + c4*4);
            cpa16(sVu + (uint32_t)(r*VSTR + c4*4)*4u, Vg + (size_t)r*DDIM + c4*4);
        }
        CP_COMMIT();
    }

    float acc_o[2][8][4] = {};
    float lsum[2][2] = {};
    const int srcA = (lane & 28) | (t >> 1);   // g*4 + t/2
    const int srcB = srcA + 2;
    const bool oddt = (t & 1);

    for (int kt = 0; kt < 16; ++kt){
        CP_WAIT(0);
        __syncthreads();                       // publish K(kt),V(kt); buffers of kt-1 free
        if (kt + 1 < 16) loadKV(kt + 1, (kt + 1) & 1);

        // ---- S = Q K^T : per warp 32q x 64k
        const uint32_t qbase = sQu + qoff;
        const uint32_t kbase = sKu + (uint32_t)((kt & 1) * QTB) * 4u + koff;
        float s[2][8][4] = {};
        #pragma unroll
        for (int kk = 0; kk < 8; ++kk){
            uint32_t qa[2][4], kq[4][4];
            #pragma unroll
            for (int mi = 0; mi < 2; ++mi)
                ldsm4(qa[mi], qbase + mi*(16*KSTR*4) + kk*32);
            #pragma unroll
            for (int p = 0; p < 4; ++p)
                ldsm4(kq[p], kbase + p*(16*KSTR*4) + kk*32);
            #pragma unroll
            for (int mi = 0; mi < 2; ++mi)
                #pragma unroll
                for (int p = 0; p < 4; ++p){
                    mma8(s[mi][2*p],     qa[mi], kq[p]);
                    mma8(s[mi][2*p + 1], qa[mi], kq[p] + 2);
                }
        }

        // ---- P = exp(S/32) in-register, tf32-rounded
        #pragma unroll
        for (int mi = 0; mi < 2; ++mi)
            #pragma unroll
            for (int ni = 0; ni < 8; ++ni)
                #pragma unroll
                for (int rr = 0; rr < 2; ++rr){
                    const float e0 = exp2f(s[mi][ni][rr*2 + 0] * 0.04508422002777998f);
                    const float e1 = exp2f(s[mi][ni][rr*2 + 1] * 0.04508422002777998f);
                    lsum[mi][rr] += e0 + e1;
                    s[mi][ni][rr*2 + 0] = f2tf32f(e0);
                    s[mi][ni][rr*2 + 1] = f2tf32f(e1);
                }

        // ---- O += P V : shuffle D-frag -> A-frag, V via scalar LDS
        const float* vbuf = sV + (kt & 1) * VTB;
        #pragma unroll
        for (int kb = 0; kb < 8; ++kb){
            uint32_t af[2][4];
            #pragma unroll
            for (int mi = 0; mi < 2; ++mi){
                const float c0 = s[mi][kb][0], c1 = s[mi][kb][1];
                const float c2 = s[mi][kb][2], c3 = s[mi][kb][3];
                const float u0 = __shfl_sync(0xffffffffu, c0, srcA);
                const float u1 = __shfl_sync(0xffffffffu, c1, srcA);
                const float w0 = __shfl_sync(0xffffffffu, c2, srcA);
                const float w1 = __shfl_sync(0xffffffffu, c3, srcA);
                const float x0 = __shfl_sync(0xffffffffu, c0, srcB);
                const float x1 = __shfl_sync(0xffffffffu, c1, srcB);
                const float y0 = __shfl_sync(0xffffffffu, c2, srcB);
                const float y1 = __shfl_sync(0xffffffffu, c3, srcB);
                af[mi][0] = __float_as_uint(oddt ? u1 : u0);
                af[mi][1] = __float_as_uint(oddt ? w1 : w0);
                af[mi][2] = __float_as_uint(oddt ? x1 : x0);
                af[mi][3] = __float_as_uint(oddt ? y1 : y0);
            }
            const float* vrow = vbuf + (wk + kb*8 + t) * VSTR + g;
            #pragma unroll
            for (int nd = 0; nd < 8; ++nd){
                uint32_t vb[2];
                vb[0] = __float_as_uint(vrow[nd*8]);
                vb[1] = __float_as_uint(vrow[nd*8 + 4*VSTR]);
                mma8(acc_o[0][nd], af[0], vb);
                mma8(acc_o[1][nd], af[1], vb);
            }
        }
    }

    // ---- epilogue: reduce across the key-warp pair
    __syncthreads();                 // all PV done; sK dead -> scratch
    float* scr = sK;                 // 128 x 64
    if (wid & 1){
        #pragma unroll
        for (int mi = 0; mi < 2; ++mi)
            #pragma unroll
            for (int rr = 0; rr < 2; ++rr){
                const int row = wm + mi*16 + g + rr*8;
                #pragma unroll
                for (int nd = 0; nd < 8; ++nd){
                    const int col = nd*8 + t*2;
                    *(float2*)(scr + row*64 + col) =
                        make_float2(acc_o[mi][nd][rr*2], acc_o[mi][nd][rr*2+1]);
                }
            }
    }
    #pragma unroll
    for (int mi = 0; mi < 2; ++mi)
        #pragma unroll
        for (int rr = 0; rr < 2; ++rr){
            float v = lsum[mi][rr];
            v += __shfl_xor_sync(0xffffffffu, v, 1);
            v += __shfl_xor_sync(0xffffffffu, v, 2);
            if (t == 0) atomicAdd(&rowsum[wm + mi*16 + g + rr*8], v);
        }
    __syncthreads();

    if (!(wid & 1)){
        #pragma unroll
        for (int mi = 0; mi < 2; ++mi)
            #pragma unroll
            for (int rr = 0; rr < 2; ++rr){
                const int row = wm + mi*16 + g + rr*8;
                const float inv = 1.0f / rowsum[row];
                float* orow = Out + ((size_t)(b * SSEQ + q0 + row)) * EEMB + h * DDIM;
                #pragma unroll
                for (int nd = 0; nd < 8; ++nd){
                    const int col = nd*8 + t*2;
                    const float2 p = *(const float2*)(scr + row*64 + col);
                    const float v0 = f2tf32f((acc_o[mi][nd][rr*2]   + p.x) * inv);
                    const float v1 = f2tf32f((acc_o[mi][nd][rr*2+1] + p.y) * inv);
                    *(float2*)(orow + col) = make_float2(v0, v1);
                }
            }
    }
}

// ---------------------------------------------------------------------------
extern "C" void kernel_launch(void* const* d_in, const int* in_sizes, int n_in,
                              void* d_out, int out_size)
{
    const float* x  = (const float*)d_in[0];
    const float* Wq = (const float*)d_in[1];
    const float* bq = (const float*)d_in[2];
    const float* Wk = (const float*)d_in[3];
    const float* bk = (const float*)d_in[4];
    const float* Wv = (const float*)d_in[5];
    const float* bv = (const float*)d_in[6];
    const float* Wo = (const float*)d_in[7];
    const float* bo = (const float*)d_in[8];
    float* out = (float*)d_out;

    float *qp, *kp, *vp, *ap;
    cudaGetSymbolAddress((void**)&qp, g_Q);
    cudaGetSymbolAddress((void**)&kp, g_K);
    cudaGetSymbolAddress((void**)&vp, g_V);
    cudaGetSymbolAddress((void**)&ap, g_A);

    const int gemm_smem = 6 * GTB * (int)sizeof(float);                 // 110592
    const int attn_smem = (3*QTB + 2*VTB) * (int)sizeof(float);         // 178176
    cudaFuncSetAttribute(gemm_qkv, cudaFuncAttributeMaxDynamicSharedMemorySize, gemm_smem);
    cudaFuncSetAttribute(gemm_out, cudaFuncAttributeMaxDynamicSharedMemorySize, gemm_smem);
    cudaFuncSetAttribute(attn_mma, cudaFuncAttributeMaxDynamicSharedMemorySize, attn_smem);

    dim3 gq(EEMB/128, MMROWS/128, 3);   // 8 x 64 x 3
    gemm_qkv<<<gq, 256, gemm_smem>>>(x, Wq, bq, Wk, bk, Wv, bv, qp, kp, vp);

    dim3 ga(SSEQ/128, BBATCH*HHEADS);   // 16 x 64
    attn_mma<<<ga, 256, attn_smem>>>(qp, kp, vp, ap);

    dim3 gg(EEMB/128, MMROWS/128);      // 8 x 64
    gemm_out<<<gg, 256, gemm_smem>>>(ap, Wo, bo, out);
}

// round 8
// speedup vs baseline: 1.1634x; 1.0594x over previous
#include <cuda_runtime.h>
#include <cstdint>
#include <math.h>

#define BBATCH 4
#define SSEQ   2048
#define EEMB   1024
#define HHEADS 16
#define DDIM   64
#define MMROWS (BBATCH*SSEQ)   // 8192

// Scratch (no allocations allowed)
__device__ float g_Q[(size_t)BBATCH*HHEADS*SSEQ*DDIM];
__device__ float g_K[(size_t)BBATCH*HHEADS*SSEQ*DDIM];
__device__ float g_V[(size_t)BBATCH*HHEADS*SSEQ*DDIM];
__device__ float g_A[(size_t)BBATCH*SSEQ*EEMB];

// ---------------------------------------------------------------- helpers
__device__ __forceinline__ uint32_t smem_u32(const void* p){
    uint32_t a;
    asm("{ .reg .u64 t; cvta.to.shared.u64 t, %1; cvt.u32.u64 %0, t; }"
        : "=r"(a) : "l"(p));
    return a;
}
__device__ __forceinline__ float f2tf32f(float x){
    uint32_t u; asm("cvt.rna.tf32.f32 %0, %1;" : "=r"(u) : "f"(x));
    return __uint_as_float(u);
}
__device__ __forceinline__ void cpa16(uint32_t dst, const void* src){
    asm volatile("cp.async.cg.shared.global [%0], [%1], 16;" :: "r"(dst), "l"(src));
}
#define CP_COMMIT() asm volatile("cp.async.commit_group;" ::: "memory")
#define CP_WAIT(n)  asm volatile("cp.async.wait_group %0;" :: "n"(n) : "memory")

// ldmatrix x4: four 8-row x 16B matrices -> 4 regs
__device__ __forceinline__ void ldsm4(uint32_t* r, uint32_t addr){
    asm volatile("ldmatrix.sync.aligned.m8n8.x4.shared.b16 {%0,%1,%2,%3}, [%4];"
        : "=r"(r[0]), "=r"(r[1]), "=r"(r[2]), "=r"(r[3]) : "r"(addr));
}

// D += A(16x8,tf32) * B(8x8,tf32), fp32 accum
__device__ __forceinline__ void mma8(float* d, const uint32_t* a, const uint32_t* b){
    asm volatile("mma.sync.aligned.m16n8k8.row.col.f32.tf32.tf32.f32 "
        "{%0,%1,%2,%3},{%4,%5,%6,%7},{%8,%9},{%0,%1,%2,%3};"
        : "+f"(d[0]), "+f"(d[1]), "+f"(d[2]), "+f"(d[3])
        : "r"(a[0]), "r"(a[1]), "r"(a[2]), "r"(a[3]), "r"(b[0]), "r"(b[1]));
}

// ---------------------------------------------------------------------------
// GEMM (unchanged, known-good): CTA 128x128, BK=32, 3-stage cp.async,
// 8 warps 64x32, ldmatrix feeds, 2 CTA/SM.
// ---------------------------------------------------------------------------
#define GSTR 36
#define GTB  (128*GSTR)

__device__ __forceinline__ void gemm_core(
    const float* __restrict__ A, const float* __restrict__ W,
    const float* __restrict__ bias, float* __restrict__ out,
    int scatter, int round_out, float* sm)
{
    float* sA = sm;
    float* sB = sm + 3*GTB;
    const uint32_t sAu = smem_u32(sA), sBu = smem_u32(sB);

    const int tid = threadIdx.x;
    const int wid = tid >> 5, lane = tid & 31;
    const int g = lane >> 2, t = lane & 3;
    const int lane7 = lane & 7, mat = lane >> 3;
    const int wm = (wid >> 2) * 64, wn = (wid & 3) * 32;
    const int m0 = blockIdx.y * 128, n0 = blockIdx.x * 128;

    const uint32_t aoff = ((uint32_t)((wm + (mat&1)*8 + lane7) * GSTR + (mat>>1)*4)) * 4u;
    const uint32_t boff = ((uint32_t)((wn + (mat>>1)*8 + lane7) * GSTR + (mat&1)*4)) * 4u;

    float acc[4][4][4] = {};

    auto prefetch = [&](int kc, int st){
        #pragma unroll
        for (int it = 0; it < 4; ++it){
            const int f = tid + it*256;
            const int r = f >> 3, c4 = f & 7;
            const uint32_t so = (uint32_t)(st*GTB + r*GSTR + c4*4) * 4u;
            cpa16(sAu + so, A + (size_t)(m0 + r) * EEMB + kc*32 + c4*4);
            cpa16(sBu + so, W + (size_t)(n0 + r) * EEMB + kc*32 + c4*4);
        }
        CP_COMMIT();
    };

    prefetch(0, 0);
    prefetch(1, 1);
    for (int kc = 0; kc < 32; ++kc){
        if (kc < 31) { CP_WAIT(1); } else { CP_WAIT(0); }
        __syncthreads();
        if (kc + 2 < 32) prefetch(kc + 2, (kc + 2) % 3);
        const uint32_t stb = (uint32_t)((kc % 3) * GTB) * 4u;
        const uint32_t abase = sAu + stb + aoff;
        const uint32_t bbase = sBu + stb + boff;
        #pragma unroll
        for (int kk = 0; kk < 4; ++kk){
            uint32_t af[4][4], bq0[4], bq1[4];
            #pragma unroll
            for (int mi = 0; mi < 4; ++mi)
                ldsm4(af[mi], abase + mi*(16*GSTR*4) + kk*32);
            ldsm4(bq0, bbase + kk*32);
            ldsm4(bq1, bbase + 16*GSTR*4 + kk*32);
            #pragma unroll
            for (int mi = 0; mi < 4; ++mi){
                mma8(acc[mi][0], af[mi], bq0);
                mma8(acc[mi][1], af[mi], bq0 + 2);
                mma8(acc[mi][2], af[mi], bq1);
                mma8(acc[mi][3], af[mi], bq1 + 2);
            }
        }
    }

    #pragma unroll
    for (int mi = 0; mi < 4; ++mi){
        #pragma unroll
        for (int ni = 0; ni < 4; ++ni){
            const int n = n0 + wn + ni*8 + t*2;
            const float bv0 = bias[n], bv1 = bias[n+1];
            #pragma unroll
            for (int rr = 0; rr < 2; ++rr){
                const int m = m0 + wm + mi*16 + g + rr*8;
                float v0 = acc[mi][ni][rr*2 + 0] + bv0;
                float v1 = acc[mi][ni][rr*2 + 1] + bv1;
                if (round_out){ v0 = f2tf32f(v0); v1 = f2tf32f(v1); }
                float* op;
                if (scatter){
                    const int b = m >> 11, s = m & 2047;
                    const int h = n >> 6, d = n & 63;
                    op = out + ((size_t)(b*HHEADS + h) * SSEQ + s) * DDIM + d;
                } else {
                    op = out + (size_t)m * EEMB + n;
                }
                *(float2*)op = make_float2(v0, v1);
            }
        }
    }
}

__global__ __launch_bounds__(256)
void gemm_qkv(const float* __restrict__ x,
              const float* __restrict__ Wq, const float* __restrict__ bq,
              const float* __restrict__ Wk, const float* __restrict__ bk,
              const float* __restrict__ Wv, const float* __restrict__ bv,
              float* __restrict__ q, float* __restrict__ k, float* __restrict__ v)
{
    extern __shared__ float sm[];
    if      (blockIdx.z == 0) gemm_core(x, Wq, bq, q, 1, 1, sm);
    else if (blockIdx.z == 1) gemm_core(x, Wk, bk, k, 1, 1, sm);
    else                      gemm_core(x, Wv, bv, v, 1, 1, sm);
}

__global__ __launch_bounds__(256)
void gemm_out(const float* __restrict__ A, const float* __restrict__ W,
              const float* __restrict__ b, float* __restrict__ out)
{
    extern __shared__ float sm[];
    gemm_core(A, W, b, out, 0, 0, sm);
}

// ---------------------------------------------------------------------------
// Attention, register-P, 64-key tiles, 2 CTAs/SM.
// 8 warps = 4 m-groups (32q) x 2 key-groups (32k per warp).
// One barrier per tile; K,V double-buffered; P never touches smem.
// ---------------------------------------------------------------------------
#define KSTR 68           // Q/K row stride (floats)
#define VSTR 72           // V row stride
#define QTB  (128*KSTR)   // Q tile floats (128 rows)
#define KTB64 (64*KSTR)   // K tile floats (64 rows)
#define VTB64 (64*VSTR)   // V tile floats (64 rows)

__global__ __launch_bounds__(256, 2)
void attn_mma(const float* __restrict__ Q, const float* __restrict__ K,
              const float* __restrict__ V, float* __restrict__ Out)
{
    extern __shared__ float sm[];
    float* sQ = sm;                      // QTB
    float* sK = sm + QTB;                // [2][KTB64]  (also O-reduction scratch)
    float* sV = sm + QTB + 2*KTB64;      // [2][VTB64]
    __shared__ float rowsum[128];
    const uint32_t sQu = smem_u32(sQ), sKu = smem_u32(sK), sVu = smem_u32(sV);

    const int tid = threadIdx.x;
    const int wid = tid >> 5, lane = tid & 31;
    const int g = lane >> 2, t = lane & 3;
    const int lane7 = lane & 7, mat = lane >> 3;
    const int wm = (wid >> 1) * 32;        // 4 m-groups of 32 q-rows
    const int wk = (wid & 1) * 32;         // 2 key-groups of 32 keys
    const int q0 = blockIdx.x * 128;
    const int bh = blockIdx.y;
    const int b = bh >> 4, h = bh & 15;

    const float* Qp = Q + (size_t)bh * SSEQ * DDIM;
    const float* Kp = K + (size_t)bh * SSEQ * DDIM;
    const float* Vp = V + (size_t)bh * SSEQ * DDIM;

    if (tid < 128) rowsum[tid] = 0.f;

    const uint32_t qoff = ((uint32_t)((wm + (mat&1)*8 + lane7) * KSTR + (mat>>1)*4)) * 4u;
    const uint32_t koff = ((uint32_t)((wk + (mat>>1)*8 + lane7) * KSTR + (mat&1)*4)) * 4u;

    auto loadKV = [&](int kt, int buf){
        const float* Kg = Kp + (size_t)kt * 64 * DDIM;
        const float* Vg = Vp + (size_t)kt * 64 * DDIM;
        #pragma unroll
        for (int it = 0; it < 4; ++it){
            const int f = tid + it*256;           // 0..1023
            const int r = f >> 4, c4 = f & 15;
            cpa16(sKu + (uint32_t)(buf*KTB64 + r*KSTR + c4*4)*4u, Kg + (size_t)r*DDIM + c4*4);
            cpa16(sVu + (uint32_t)(buf*VTB64 + r*VSTR + c4*4)*4u, Vg + (size_t)r*DDIM + c4*4);
        }
        CP_COMMIT();
    };

    // prologue: Q + K0/V0 in one group
    #pragma unroll
    for (int it = 0; it < 8; ++it){
        const int f = tid + it*256;
        const int r = f >> 4, c4 = f & 15;
        cpa16(sQu + (uint32_t)(r*KSTR + c4*4)*4u, Qp + (size_t)(q0 + r)*DDIM + c4*4);
    }
    #pragma unroll
    for (int it = 0; it < 4; ++it){
        const int f = tid + it*256;
        const int r = f >> 4, c4 = f & 15;
        cpa16(sKu + (uint32_t)(r*KSTR + c4*4)*4u, Kp + (size_t)r*DDIM + c4*4);
        cpa16(sVu + (uint32_t)(r*VSTR + c4*4)*4u, Vp + (size_t)r*DDIM + c4*4);
    }
    CP_COMMIT();

    float acc_o[2][8][4] = {};
    float lsum[2][2] = {};
    const int srcA = (lane & 28) | (t >> 1);   // g*4 + t/2
    const int srcB = srcA + 2;
    const bool oddt = (t & 1);

    for (int kt = 0; kt < 32; ++kt){
        CP_WAIT(0);
        __syncthreads();                       // publish K(kt),V(kt)
        if (kt + 1 < 32) loadKV(kt + 1, (kt + 1) & 1);

        // ---- S = Q K^T : per warp 32q x 32k
        const uint32_t qbase = sQu + qoff;
        const uint32_t kbase = sKu + (uint32_t)((kt & 1) * KTB64) * 4u + koff;
        float s[2][4][4] = {};
        #pragma unroll
        for (int kk = 0; kk < 8; ++kk){
            uint32_t qa[2][4], kq[2][4];
            #pragma unroll
            for (int mi = 0; mi < 2; ++mi)
                ldsm4(qa[mi], qbase + mi*(16*KSTR*4) + kk*32);
            #pragma unroll
            for (int p = 0; p < 2; ++p)
                ldsm4(kq[p], kbase + p*(16*KSTR*4) + kk*32);
            #pragma unroll
            for (int mi = 0; mi < 2; ++mi)
                #pragma unroll
                for (int p = 0; p < 2; ++p){
                    mma8(s[mi][2*p],     qa[mi], kq[p]);
                    mma8(s[mi][2*p + 1], qa[mi], kq[p] + 2);
                }
        }

        // ---- P = exp(S/32) in-register, tf32-rounded
        #pragma unroll
        for (int mi = 0; mi < 2; ++mi)
            #pragma unroll
            for (int ni = 0; ni < 4; ++ni)
                #pragma unroll
                for (int rr = 0; rr < 2; ++rr){
                    const float e0 = exp2f(s[mi][ni][rr*2 + 0] * 0.04508422002777998f);
                    const float e1 = exp2f(s[mi][ni][rr*2 + 1] * 0.04508422002777998f);
                    lsum[mi][rr] += e0 + e1;
                    s[mi][ni][rr*2 + 0] = f2tf32f(e0);
                    s[mi][ni][rr*2 + 1] = f2tf32f(e1);
                }

        // ---- O += P V : shuffle D-frag -> A-frag, V via scalar LDS
        const float* vbuf = sV + (kt & 1) * VTB64;
        #pragma unroll
        for (int kb = 0; kb < 4; ++kb){
            uint32_t af[2][4];
            #pragma unroll
            for (int mi = 0; mi < 2; ++mi){
                const float c0 = s[mi][kb][0], c1 = s[mi][kb][1];
                const float c2 = s[mi][kb][2], c3 = s[mi][kb][3];
                const float u0 = __shfl_sync(0xffffffffu, c0, srcA);
                const float u1 = __shfl_sync(0xffffffffu, c1, srcA);
                const float w0 = __shfl_sync(0xffffffffu, c2, srcA);
                const float w1 = __shfl_sync(0xffffffffu, c3, srcA);
                const float x0 = __shfl_sync(0xffffffffu, c0, srcB);
                const float x1 = __shfl_sync(0xffffffffu, c1, srcB);
                const float y0 = __shfl_sync(0xffffffffu, c2, srcB);
                const float y1 = __shfl_sync(0xffffffffu, c3, srcB);
                af[mi][0] = __float_as_uint(oddt ? u1 : u0);
                af[mi][1] = __float_as_uint(oddt ? w1 : w0);
                af[mi][2] = __float_as_uint(oddt ? x1 : x0);
                af[mi][3] = __float_as_uint(oddt ? y1 : y0);
            }
            const float* vrow = vbuf + (wk + kb*8 + t) * VSTR + g;
            #pragma unroll
            for (int nd = 0; nd < 8; ++nd){
                uint32_t vb[2];
                vb[0] = __float_as_uint(vrow[nd*8]);
                vb[1] = __float_as_uint(vrow[nd*8 + 4*VSTR]);
                mma8(acc_o[0][nd], af[0], vb);
                mma8(acc_o[1][nd], af[1], vb);
            }
        }
    }

    // ---- epilogue: reduce across the key-warp pair
    __syncthreads();                 // all PV done; sK/sV dead -> scratch
    float* scr = sK;                 // 128 x 64 = 32KB <= 2*KTB64+... fits
    if (wid & 1){
        #pragma unroll
        for (int mi = 0; mi < 2; ++mi)
            #pragma unroll
            for (int rr = 0; rr < 2; ++rr){
                const int row = wm + mi*16 + g + rr*8;
                #pragma unroll
                for (int nd = 0; nd < 8; ++nd){
                    const int col = nd*8 + t*2;
                    *(float2*)(scr + row*64 + col) =
                        make_float2(acc_o[mi][nd][rr*2], acc_o[mi][nd][rr*2+1]);
                }
            }
    }
    #pragma unroll
    for (int mi = 0; mi < 2; ++mi)
        #pragma unroll
        for (int rr = 0; rr < 2; ++rr){
            float v = lsum[mi][rr];
            v += __shfl_xor_sync(0xffffffffu, v, 1);
            v += __shfl_xor_sync(0xffffffffu, v, 2);
            if (t == 0) atomicAdd(&rowsum[wm + mi*16 + g + rr*8], v);
        }
    __syncthreads();

    if (!(wid & 1)){
        #pragma unroll
        for (int mi = 0; mi < 2; ++mi)
            #pragma unroll
            for (int rr = 0; rr < 2; ++rr){
                const int row = wm + mi*16 + g + rr*8;
                const float inv = 1.0f / rowsum[row];
                float* orow = Out + ((size_t)(b * SSEQ + q0 + row)) * EEMB + h * DDIM;
                #pragma unroll
                for (int nd = 0; nd < 8; ++nd){
                    const int col = nd*8 + t*2;
                    const float2 p = *(const float2*)(scr + row*64 + col);
                    const float v0 = f2tf32f((acc_o[mi][nd][rr*2]   + p.x) * inv);
                    const float v1 = f2tf32f((acc_o[mi][nd][rr*2+1] + p.y) * inv);
                    *(float2*)(orow + col) = make_float2(v0, v1);
                }
            }
    }
}

// ---------------------------------------------------------------------------
extern "C" void kernel_launch(void* const* d_in, const int* in_sizes, int n_in,
                              void* d_out, int out_size)
{
    const float* x  = (const float*)d_in[0];
    const float* Wq = (const float*)d_in[1];
    const float* bq = (const float*)d_in[2];
    const float* Wk = (const float*)d_in[3];
    const float* bk = (const float*)d_in[4];
    const float* Wv = (const float*)d_in[5];
    const float* bv = (const float*)d_in[6];
    const float* Wo = (const float*)d_in[7];
    const float* bo = (const float*)d_in[8];
    float* out = (float*)d_out;

    float *qp, *kp, *vp, *ap;
    cudaGetSymbolAddress((void**)&qp, g_Q);
    cudaGetSymbolAddress((void**)&kp, g_K);
    cudaGetSymbolAddress((void**)&vp, g_V);
    cudaGetSymbolAddress((void**)&ap, g_A);

    const int gemm_smem = 6 * GTB * (int)sizeof(float);                       // 110592
    const int attn_smem = (QTB + 2*KTB64 + 2*VTB64) * (int)sizeof(float);     // 106496
    cudaFuncSetAttribute(gemm_qkv, cudaFuncAttributeMaxDynamicSharedMemorySize, gemm_smem);
    cudaFuncSetAttribute(gemm_out, cudaFuncAttributeMaxDynamicSharedMemorySize, gemm_smem);
    cudaFuncSetAttribute(attn_mma, cudaFuncAttributeMaxDynamicSharedMemorySize, attn_smem);

    dim3 gq(EEMB/128, MMROWS/128, 3);   // 8 x 64 x 3
    gemm_qkv<<<gq, 256, gemm_smem>>>(x, Wq, bq, Wk, bk, Wv, bv, qp, kp, vp);

    dim3 ga(SSEQ/128, BBATCH*HHEADS);   // 16 x 64
    attn_mma<<<ga, 256, attn_smem>>>(qp, kp, vp, ap);

    dim3 gg(EEMB/128, MMROWS/128);      // 8 x 64
    gemm_out<<<gg, 256, gemm_smem>>>(ap, Wo, bo, out);
}

// round 9
// speedup vs baseline: 2.0591x; 1.7699x over previous
#include <cuda_runtime.h>
#include <cuda_fp16.h>
#include <cstdint>
#include <math.h>

#define BBATCH 4
#define SSEQ   2048
#define EEMB   1024
#define HHEADS 16
#define DDIM   64
#define MMROWS (BBATCH*SSEQ)   // 8192

// fp16 scratch (no allocations allowed)
__device__ __half g_xh[(size_t)MMROWS*EEMB];
__device__ __half g_Wqh[(size_t)EEMB*EEMB];
__device__ __half g_Wkh[(size_t)EEMB*EEMB];
__device__ __half g_Wvh[(size_t)EEMB*EEMB];
__device__ __half g_Woh[(size_t)EEMB*EEMB];
__device__ __half g_Qh[(size_t)BBATCH*HHEADS*SSEQ*DDIM];
__device__ __half g_Kh[(size_t)BBATCH*HHEADS*SSEQ*DDIM];
__device__ __half g_Vh[(size_t)BBATCH*HHEADS*SSEQ*DDIM];
__device__ __half g_Ah[(size_t)BBATCH*SSEQ*EEMB];

// ---------------------------------------------------------------- helpers
__device__ __forceinline__ uint32_t smem_u32(const void* p){
    uint32_t a;
    asm("{ .reg .u64 t; cvta.to.shared.u64 t, %1; cvt.u32.u64 %0, t; }"
        : "=r"(a) : "l"(p));
    return a;
}
__device__ __forceinline__ void cpa16(uint32_t dst, const void* src){
    asm volatile("cp.async.cg.shared.global [%0], [%1], 16;" :: "r"(dst), "l"(src));
}
#define CP_COMMIT() asm volatile("cp.async.commit_group;" ::: "memory")
#define CP_WAIT(n)  asm volatile("cp.async.wait_group %0;" :: "n"(n) : "memory")

__device__ __forceinline__ void ldsm4(uint32_t* r, uint32_t addr){
    asm volatile("ldmatrix.sync.aligned.m8n8.x4.shared.b16 {%0,%1,%2,%3}, [%4];"
        : "=r"(r[0]), "=r"(r[1]), "=r"(r[2]), "=r"(r[3]) : "r"(addr));
}
__device__ __forceinline__ void ldsm4t(uint32_t* r, uint32_t addr){
    asm volatile("ldmatrix.sync.aligned.m8n8.x4.trans.shared.b16 {%0,%1,%2,%3}, [%4];"
        : "=r"(r[0]), "=r"(r[1]), "=r"(r[2]), "=r"(r[3]) : "r"(addr));
}
// D += A(16x16,f16) * B(16x8,f16), fp32 accum
__device__ __forceinline__ void mma16(float* d, const uint32_t* a, uint32_t b0, uint32_t b1){
    asm volatile("mma.sync.aligned.m16n8k16.row.col.f32.f16.f16.f32 "
        "{%0,%1,%2,%3},{%4,%5,%6,%7},{%8,%9},{%0,%1,%2,%3};"
        : "+f"(d[0]), "+f"(d[1]), "+f"(d[2]), "+f"(d[3])
        : "r"(a[0]), "r"(a[1]), "r"(a[2]), "r"(a[3]), "r"(b0), "r"(b1));
}
__device__ __forceinline__ uint32_t pkh2(float lo, float hi){
    __half2 h = __floats2half2_rn(lo, hi);
    return *reinterpret_cast<uint32_t*>(&h);
}

// ---------------------------------------------------------------------------
// fp32 -> fp16 converter (grid-stride, float4 granularity)
// ---------------------------------------------------------------------------
__global__ void f2h(const float* __restrict__ src, __half* __restrict__ dst, int n4){
    for (int i = blockIdx.x*blockDim.x + threadIdx.x; i < n4; i += gridDim.x*blockDim.x){
        float4 v = ((const float4*)src)[i];
        uint2 o;
        o.x = pkh2(v.x, v.y);
        o.y = pkh2(v.z, v.w);
        ((uint2*)dst)[i] = o;
    }
}

// ---------------------------------------------------------------------------
// fp16 GEMM: out = A(Mx1024) @ W(Nx1024)^T + bias.  CTA 128x128, BK=64,
// 2-stage cp.async, 8 warps 64x32 (m16n8k16), ldmatrix feeds, 2 CTA/SM.
// mode 1: scatter fp16 to [B,H,S,D];  mode 0: fp32 row-major MxN.
// ---------------------------------------------------------------------------
#define SG 18432   // stage bytes: 128 rows x 144B (64 halves data + 8 pad)

__device__ __forceinline__ void gemm_core_h(
    const __half* __restrict__ A, const __half* __restrict__ W,
    const float* __restrict__ bias, void* __restrict__ outp,
    int half_scatter, char* smc)
{
    const uint32_t sAu = smem_u32(smc);
    const uint32_t sBu = sAu + 2*SG;

    const int tid = threadIdx.x;
    const int wid = tid >> 5, lane = tid & 31;
    const int g = lane >> 2, t = lane & 3;
    const int lane7 = lane & 7;
    const int wm = (wid >> 2) * 64, wn = (wid & 3) * 32;
    const int m0 = blockIdx.y * 128, n0 = blockIdx.x * 128;

    // ldsm lane offsets (bytes): row = base + ((lane>>3)&1)*8 + lane7, col16B = lane>>4
    const uint32_t lrow = ((uint32_t)(((lane>>3)&1)*8 + lane7)) * 144u + ((uint32_t)(lane>>4))*16u;
    const uint32_t aoff = (uint32_t)wm*144u + lrow;
    const uint32_t boff = (uint32_t)wn*144u + lrow;

    float acc[4][4][4] = {};

    auto prefetch = [&](int kc, int st){
        const __half* Ag = A + (size_t)m0*EEMB + kc*64;
        const __half* Wg = W + (size_t)n0*EEMB + kc*64;
        #pragma unroll
        for (int it = 0; it < 4; ++it){
            const int f = tid + it*256;      // 0..1023
            const int r = f >> 3, c = f & 7;
            const uint32_t so = (uint32_t)(st*SG + r*144 + c*16);
            cpa16(sAu + so, Ag + (size_t)r*EEMB + c*8);
            cpa16(sBu + so, Wg + (size_t)r*EEMB + c*8);
        }
        CP_COMMIT();
    };

    prefetch(0, 0);
    for (int kc = 0; kc < 16; ++kc){
        CP_WAIT(0);
        __syncthreads();
        if (kc + 1 < 16) prefetch(kc + 1, (kc + 1) & 1);
        const uint32_t ab = sAu + (uint32_t)((kc & 1) * SG) + aoff;
        const uint32_t bb = sBu + (uint32_t)((kc & 1) * SG) + boff;
        #pragma unroll
        for (int kk = 0; kk < 4; ++kk){
            uint32_t af[4][4], bf[2][4];
            #pragma unroll
            for (int mi = 0; mi < 4; ++mi)
                ldsm4(af[mi], ab + mi*(16*144) + kk*32);
            #pragma unroll
            for (int p = 0; p < 2; ++p)
                ldsm4(bf[p], bb + p*(16*144) + kk*32);
            #pragma unroll
            for (int mi = 0; mi < 4; ++mi)
                #pragma unroll
                for (int p = 0; p < 2; ++p){
                    mma16(acc[mi][2*p],     af[mi], bf[p][0], bf[p][2]);
                    mma16(acc[mi][2*p + 1], af[mi], bf[p][1], bf[p][3]);
                }
        }
    }

    // epilogue
    #pragma unroll
    for (int mi = 0; mi < 4; ++mi){
        #pragma unroll
        for (int ni = 0; ni < 4; ++ni){
            const int n = n0 + wn + ni*8 + t*2;
            const float bv0 = bias[n], bv1 = bias[n+1];
            #pragma unroll
            for (int rr = 0; rr < 2; ++rr){
                const int m = m0 + wm + mi*16 + g + rr*8;
                const float v0 = acc[mi][ni][rr*2 + 0] + bv0;
                const float v1 = acc[mi][ni][rr*2 + 1] + bv1;
                if (half_scatter){
                    const int b = m >> 11, s = m & 2047;
                    const int h = n >> 6, d = n & 63;
                    __half* op = (__half*)outp + (((size_t)(b*HHEADS + h) * SSEQ + s) * DDIM + d);
                    *(__half2*)op = __floats2half2_rn(v0, v1);
                } else {
                    float* op = (float*)outp + ((size_t)m * EEMB + n);
                    *(float2*)op = make_float2(v0, v1);
                }
            }
        }
    }
}

__global__ __launch_bounds__(256)
void gemm_qkv(const float* __restrict__ bq, const float* __restrict__ bk,
              const float* __restrict__ bv)
{
    extern __shared__ char smc[];
    if      (blockIdx.z == 0) gemm_core_h(g_xh, g_Wqh, bq, g_Qh, 1, smc);
    else if (blockIdx.z == 1) gemm_core_h(g_xh, g_Wkh, bk, g_Kh, 1, smc);
    else                      gemm_core_h(g_xh, g_Wvh, bv, g_Vh, 1, smc);
}

__global__ __launch_bounds__(256)
void gemm_out(const float* __restrict__ bo, float* __restrict__ out)
{
    extern __shared__ char smc[];
    gemm_core_h(g_Ah, g_Woh, bo, out, 0, smc);
}

// ---------------------------------------------------------------------------
// fp16 attention: per (b,h), 128q x 64-key tiles.  8 warps x 16q each, every
// warp does all 64 keys + all 64 d -> no cross-warp reduction, no epilogue
// barrier.  K,V double-buffered, one barrier per tile.  P = packed S frags.
// ---------------------------------------------------------------------------
#define QSG  18432      // Q: 128 rows x 144B
#define KVSG 9216       // K/V tile: 64 rows x 144B

__global__ __launch_bounds__(256, 2)
void attn_h(__half* __restrict__ Out)
{
    extern __shared__ char smc[];
    const uint32_t sQu = smem_u32(smc);
    const uint32_t sKu = sQu + QSG;            // [2][KVSG]
    const uint32_t sVu = sKu + 2*KVSG;         // [2][KVSG]

    const int tid = threadIdx.x;
    const int wid = tid >> 5, lane = tid & 31;
    const int g = lane >> 2, t = lane & 3;
    const int lane7 = lane & 7;
    const int q0 = blockIdx.x * 128;
    const int bh = blockIdx.y;
    const int b = bh >> 4, h = bh & 15;

    const __half* Qp = g_Qh + (size_t)bh * SSEQ * DDIM;
    const __half* Kp = g_Kh + (size_t)bh * SSEQ * DDIM;
    const __half* Vp = g_Vh + (size_t)bh * SSEQ * DDIM;

    const uint32_t lrow = ((uint32_t)(((lane>>3)&1)*8 + lane7)) * 144u + ((uint32_t)(lane>>4))*16u;
    const uint32_t qoff = (uint32_t)(wid*16)*144u + lrow;   // A-frag rows

    auto loadKV = [&](int kt, int buf){
        const __half* Kg = Kp + (size_t)kt * 64 * DDIM;
        const __half* Vg = Vp + (size_t)kt * 64 * DDIM;
        #pragma unroll
        for (int it = 0; it < 2; ++it){
            const int f = tid + it*256;        // 0..511
            const int r = f >> 3, c = f & 7;
            const uint32_t so = (uint32_t)(buf*KVSG + r*144 + c*16);
            cpa16(sKu + so, Kg + (size_t)r*DDIM + c*8);
            cpa16(sVu + so, Vg + (size_t)r*DDIM + c*8);
        }
        CP_COMMIT();
    };

    // prologue: Q + K0/V0 in one group
    #pragma unroll
    for (int it = 0; it < 4; ++it){
        const int f = tid + it*256;            // 0..1023
        const int r = f >> 3, c = f & 7;
        cpa16(sQu + (uint32_t)(r*144 + c*16), Qp + (size_t)(q0 + r)*DDIM + c*8);
    }
    #pragma unroll
    for (int it = 0; it < 2; ++it){
        const int f = tid + it*256;
        const int r = f >> 3, c = f & 7;
        cpa16(sKu + (uint32_t)(r*144 + c*16), Kp + (size_t)r*DDIM + c*8);
        cpa16(sVu + (uint32_t)(r*144 + c*16), Vp + (size_t)r*DDIM + c*8);
    }
    CP_COMMIT();

    float acc_o[8][4] = {};
    float lsum[2] = {0.f, 0.f};

    for (int kt = 0; kt < 32; ++kt){
        CP_WAIT(0);
        __syncthreads();
        if (kt + 1 < 32) loadKV(kt + 1, (kt + 1) & 1);

        // ---- S = Q K^T : 16q x 64k per warp, d=64 (4 k16 steps)
        const uint32_t qb = sQu + qoff;
        const uint32_t kb = sKu + (uint32_t)((kt & 1) * KVSG) + lrow;
        float s[8][4] = {};
        #pragma unroll
        for (int kk = 0; kk < 4; ++kk){
            uint32_t qa[4], kf[4][4];
            ldsm4(qa, qb + kk*32);
            #pragma unroll
            for (int p = 0; p < 4; ++p)
                ldsm4(kf[p], kb + p*(16*144) + kk*32);
            #pragma unroll
            for (int p = 0; p < 4; ++p){
                mma16(s[2*p],     qa, kf[p][0], kf[p][2]);
                mma16(s[2*p + 1], qa, kf[p][1], kf[p][3]);
            }
        }

        // ---- P = exp(S/32) = exp2(S * 0.03125*log2e), fp32
        #pragma unroll
        for (int ni = 0; ni < 8; ++ni)
            #pragma unroll
            for (int rr = 0; rr < 2; ++rr){
                const float e0 = exp2f(s[ni][rr*2 + 0] * 0.04508422002777998f);
                const float e1 = exp2f(s[ni][rr*2 + 1] * 0.04508422002777998f);
                lsum[rr] += e0 + e1;
                s[ni][rr*2 + 0] = e0;
                s[ni][rr*2 + 1] = e1;
            }

        // ---- O += P V : A-frags are packed S D-frags (no shuffle), V via
        // ldmatrix.trans
        const uint32_t vb = sVu + (uint32_t)((kt & 1) * KVSG) + lrow;
        #pragma unroll
        for (int kb2 = 0; kb2 < 4; ++kb2){
            uint32_t pa[4];
            pa[0] = pkh2(s[2*kb2][0],     s[2*kb2][1]);
            pa[1] = pkh2(s[2*kb2][2],     s[2*kb2][3]);
            pa[2] = pkh2(s[2*kb2 + 1][0], s[2*kb2 + 1][1]);
            pa[3] = pkh2(s[2*kb2 + 1][2], s[2*kb2 + 1][3]);
            #pragma unroll
            for (int dg = 0; dg < 4; ++dg){
                uint32_t vf[4];
                ldsm4t(vf, vb + kb2*(16*144) + dg*32);
                mma16(acc_o[2*dg],     pa, vf[0], vf[1]);
                mma16(acc_o[2*dg + 1], pa, vf[2], vf[3]);
            }
        }
    }

    // ---- epilogue: quad-reduce row sums, normalize, write fp16 A
    #pragma unroll
    for (int rr = 0; rr < 2; ++rr){
        float v = lsum[rr];
        v += __shfl_xor_sync(0xffffffffu, v, 1);
        v += __shfl_xor_sync(0xffffffffu, v, 2);
        const float inv = 1.0f / v;
        const int row = wid*16 + g + rr*8;
        __half* orow = Out + ((size_t)(b * SSEQ + q0 + row)) * EEMB + h * DDIM;
        #pragma unroll
        for (int nd = 0; nd < 8; ++nd){
            const int col = nd*8 + t*2;
            *(__half2*)(orow + col) =
                __floats2half2_rn(acc_o[nd][rr*2] * inv, acc_o[nd][rr*2+1] * inv);
        }
    }
}

// ---------------------------------------------------------------------------
extern "C" void kernel_launch(void* const* d_in, const int* in_sizes, int n_in,
                              void* d_out, int out_size)
{
    const float* x  = (const float*)d_in[0];
    const float* Wq = (const float*)d_in[1];
    const float* bq = (const float*)d_in[2];
    const float* Wk = (const float*)d_in[3];
    const float* bk = (const float*)d_in[4];
    const float* Wv = (const float*)d_in[5];
    const float* bv = (const float*)d_in[6];
    const float* Wo = (const float*)d_in[7];
    const float* bo = (const float*)d_in[8];
    float* out = (float*)d_out;

    __half *xh, *wqh, *wkh, *wvh, *woh;
    cudaGetSymbolAddress((void**)&xh,  g_xh);
    cudaGetSymbolAddress((void**)&wqh, g_Wqh);
    cudaGetSymbolAddress((void**)&wkh, g_Wkh);
    cudaGetSymbolAddress((void**)&wvh, g_Wvh);
    cudaGetSymbolAddress((void**)&woh, g_Woh);

    // fp32 -> fp16 prep
    f2h<<<2048, 256>>>(x,  xh,  (MMROWS*EEMB)/4);
    f2h<<<1024, 256>>>(Wq, wqh, (EEMB*EEMB)/4);
    f2h<<<1024, 256>>>(Wk, wkh, (EEMB*EEMB)/4);
    f2h<<<1024, 256>>>(Wv, wvh, (EEMB*EEMB)/4);
    f2h<<<1024, 256>>>(Wo, woh, (EEMB*EEMB)/4);

    const int gemm_smem = 4 * SG;                 // 73728
    const int attn_smem = QSG + 4 * KVSG;         // 55296
    cudaFuncSetAttribute(gemm_qkv, cudaFuncAttributeMaxDynamicSharedMemorySize, gemm_smem);
    cudaFuncSetAttribute(gemm_out, cudaFuncAttributeMaxDynamicSharedMemorySize, gemm_smem);
    cudaFuncSetAttribute(attn_h,   cudaFuncAttributeMaxDynamicSharedMemorySize, attn_smem);

    dim3 gq(EEMB/128, MMROWS/128, 3);   // 8 x 64 x 3
    gemm_qkv<<<gq, 256, gemm_smem>>>(bq, bk, bv);

    __half* ah;
    cudaGetSymbolAddress((void**)&ah, g_Ah);
    dim3 ga(SSEQ/128, BBATCH*HHEADS);   // 16 x 64
    attn_h<<<ga, 256, attn_smem>>>(ah);

    dim3 gg(EEMB/128, MMROWS/128);      // 8 x 64
    gemm_out<<<gg, 256, gemm_smem>>>(bo, out);
}